// round 8
// baseline (speedup 1.0000x reference)
#include <cuda_runtime.h>
#include <cuda_bf16.h>

#define B_  256
#define T_  200
#define C_  40
#define H1_ 512
#define H2_ 256
#define O_  12

// Pre-transposed weights (column-gather friendly). Static device scratch: allowed.
__device__ float g_WrecT[H1_ * H1_];   // [j][h]  (1 MB)
__device__ float g_W2T[H1_ * H2_];     // [j][h2] (512 KB)

// ---------------------------------------------------------------------------
// One-time (per launch) transpose of Wrec and W2 so that spike-gathers read
// contiguous rows: I1 += WrecT[j][:], I2 += W2T[j][:].
// ---------------------------------------------------------------------------
__global__ void snn_transpose_kernel(const float* __restrict__ Wrec,
                                     const float* __restrict__ W2)
{
    int idx = blockIdx.x * blockDim.x + threadIdx.x;
    const int n1 = H1_ * H1_;
    const int n2 = H1_ * H2_;
    if (idx < n1) {
        int j = idx >> 9;          // /512
        int h = idx & (H1_ - 1);
        g_WrecT[idx] = Wrec[h * H1_ + j];
    } else if (idx < n1 + n2) {
        int k  = idx - n1;
        int j  = k >> 8;           // /256
        int h2 = k & (H2_ - 1);
        g_W2T[k] = W2[h2 * H1_ + j];
    }
}

// ---------------------------------------------------------------------------
// Persistent-per-sample SNN kernel. Each block owns 2 batch samples and runs
// the full T=200 recurrence locally. 512 threads:
//   - all threads:   layer-1 neuron h = tid (both samples)
//   - tid < 256:     layer-2 neuron h2 = tid (both samples)
//   - tid < 24:      output unit (s = tid/12, o = tid%12)
// Spikes exchanged within the block as ballot bitmasks in SMEM.
// ---------------------------------------------------------------------------
__global__ void __launch_bounds__(512, 1)
snn_main_kernel(const float* __restrict__ x,
                const float* __restrict__ W1,
                const float* __restrict__ Wout,
                const float* __restrict__ alpha1,
                const float* __restrict__ rho1,
                const float* __restrict__ ba1,
                const float* __restrict__ alpha2,
                const float* __restrict__ rho2,
                const float* __restrict__ ba2,
                const float* __restrict__ beta_out,
                float* __restrict__ out)
{
    __shared__ float    xsh[2][C_];
    __shared__ unsigned mask1[2][16];      // layer-1 spikes, 512 bits / sample
    __shared__ unsigned mask2[2][8];       // layer-2 spikes, 256 bits / sample
    __shared__ float    woutT[H2_][O_];    // Wout transposed: [h2][o] (12 KB)

    const int tid  = threadIdx.x;
    const int lane = tid & 31;
    const int warp = tid >> 5;
    const int s0   = blockIdx.x * 2;       // first of our two samples
    const int h    = tid;                  // layer-1 neuron index

    // ---- one-time: W1 row into registers (time-invariant per thread) ----
    float w1r[C_];
    {
        const float4* p = reinterpret_cast<const float4*>(W1 + h * C_); // 160h bytes, 16B aligned
        #pragma unroll
        for (int i = 0; i < C_ / 4; i++) {
            float4 v = p[i];
            w1r[4*i+0] = v.x; w1r[4*i+1] = v.y;
            w1r[4*i+2] = v.z; w1r[4*i+3] = v.w;
        }
    }
    // ---- one-time: Wout -> SMEM transposed ----
    for (int i = tid; i < H2_ * O_; i += 512) {
        int o  = i % O_;
        int h2 = i / O_;
        woutT[h2][o] = Wout[o * H2_ + h2];
    }
    // ---- zero spike masks ----
    if (tid < 16)      { mask1[0][tid] = 0u; mask1[1][tid] = 0u; }
    else if (tid < 24) { mask2[0][tid - 16] = 0u; }
    else if (tid < 32) { mask2[1][tid - 24] = 0u; }

    // ---- per-thread state & params ----
    const float al1 = alpha1[h], rh1 = rho1[h], bs1 = ba1[h];
    float v1a = 0.f, v1b = 0.f, a1a = 0.f, a1b = 0.f;
    float spa = 0.f, spb = 0.f;            // previous-step layer-1 spikes (0/1)

    float al2 = 0.f, rh2 = 0.f, bs2 = 0.f;
    float v2a = 0.f, v2b = 0.f, a2a = 0.f, a2b = 0.f;
    if (tid < H2_) { al2 = alpha2[tid]; rh2 = rho2[tid]; bs2 = ba2[tid]; }

    const float beta = beta_out[0];
    float vout = 0.f, osum = 0.f;

    __syncthreads();

    for (int t = 0; t < T_; t++) {
        // -------- stage x_t for both samples --------
        if (tid < 2 * C_) {
            int s = tid / C_, c = tid % C_;
            xsh[s][c] = x[(s0 + s) * (T_ * C_) + t * C_ + c];
        }
        __syncthreads();  // B1: xsh ready; prev-step consumers of xsh/masks done

        // -------- layer 1: input drive (dense, register-resident weights) --------
        float i0a = 0.f, i1a = 0.f, i2a = 0.f, i3a = 0.f;
        float i0b = 0.f, i1b = 0.f, i2b = 0.f, i3b = 0.f;
        #pragma unroll
        for (int c = 0; c < C_; c += 4) {
            i0a += w1r[c+0] * xsh[0][c+0];
            i1a += w1r[c+1] * xsh[0][c+1];
            i2a += w1r[c+2] * xsh[0][c+2];
            i3a += w1r[c+3] * xsh[0][c+3];
            i0b += w1r[c+0] * xsh[1][c+0];
            i1b += w1r[c+1] * xsh[1][c+1];
            i2b += w1r[c+2] * xsh[1][c+2];
            i3b += w1r[c+3] * xsh[1][c+3];
        }
        float I1a = (i0a + i1a) + (i2a + i3a);
        float I1b = (i0b + i1b) + (i2b + i3b);

        // -------- layer 1: recurrent drive (sparse gather over prev spikes) ----
        #pragma unroll 1
        for (int w = 0; w < 16; w++) {
            unsigned m = mask1[0][w];
            while (m) { int j = w * 32 + (__ffs(m) - 1); I1a += g_WrecT[j * H1_ + h]; m &= m - 1; }
            m = mask1[1][w];
            while (m) { int j = w * 32 + (__ffs(m) - 1); I1b += g_WrecT[j * H1_ + h]; m &= m - 1; }
        }
        __syncthreads();  // B2: all mask1 (prev) reads complete before overwrite

        // -------- layer 1: state update + spike --------
        v1a = al1 * (v1a - spa) + (1.f - al1) * (I1a - a1a);   // TH = 1.0
        v1b = al1 * (v1b - spb) + (1.f - al1) * (I1b - a1b);
        spa = (v1a - 1.0f >= 0.f) ? 1.f : 0.f;
        spb = (v1b - 1.0f >= 0.f) ? 1.f : 0.f;
        a1a = rh1 * a1a + bs1 * spa;
        a1b = rh1 * a1b + bs1 * spb;
        unsigned b1a = __ballot_sync(0xffffffffu, spa > 0.f);
        unsigned b1b = __ballot_sync(0xffffffffu, spb > 0.f);
        if (lane == 0) { mask1[0][warp] = b1a; mask1[1][warp] = b1b; }
        __syncthreads();  // B3: new mask1 visible

        // -------- layer 2 (tid < 256): gather over NEW layer-1 spikes --------
        if (tid < H2_) {
            float I2a = 0.f, I2b = 0.f;
            #pragma unroll 1
            for (int w = 0; w < 16; w++) {
                unsigned m = mask1[0][w];
                while (m) { int j = w * 32 + (__ffs(m) - 1); I2a += g_W2T[j * H2_ + tid]; m &= m - 1; }
                m = mask1[1][w];
                while (m) { int j = w * 32 + (__ffs(m) - 1); I2b += g_W2T[j * H2_ + tid]; m &= m - 1; }
            }
            v2a = al2 * v2a + (1.f - al2) * (I2a - a2a);       // no reset term (per reference)
            v2b = al2 * v2b + (1.f - al2) * (I2b - a2b);
            float s2a = (v2a - 1.0f >= 0.f) ? 1.f : 0.f;
            float s2b = (v2b - 1.0f >= 0.f) ? 1.f : 0.f;
            a2a = rh2 * a2a + bs2 * s2a;
            a2b = rh2 * a2b + bs2 * s2b;
            unsigned b2a = __ballot_sync(0xffffffffu, s2a > 0.f);
            unsigned b2b = __ballot_sync(0xffffffffu, s2b > 0.f);
            if (lane == 0) { mask2[0][warp] = b2a; mask2[1][warp] = b2b; }
        }
        __syncthreads();  // B4: mask2 visible

        // -------- output layer (tid < 24) --------
        if (tid < 2 * O_) {
            int s = tid / O_, o = tid % O_;
            float Io = 0.f;
            #pragma unroll 1
            for (int w = 0; w < 8; w++) {
                unsigned m = mask2[s][w];
                while (m) { int h2 = w * 32 + (__ffs(m) - 1); Io += woutT[h2][o]; m &= m - 1; }
            }
            vout = beta * vout + (1.f - beta) * Io;
            osum += vout;
        }
        // No barrier needed here: next step's writers to xsh/mask2 are ordered
        // behind B1/B3 of step t+1, which all readers of step t have passed.
    }

    if (tid < 2 * O_) {
        int s = tid / O_, o = tid % O_;
        out[(s0 + s) * O_ + o] = osum / (float)T_;
    }
}

// ---------------------------------------------------------------------------
// Inputs (metadata order): 0:x  1:W1  2:Wrec  3:W2  4:Wout
//                          5:alpha1 6:rho1 7:ba1 8:alpha2 9:rho2 10:ba2
//                          11:beta_out   output: float [256,12]
// ---------------------------------------------------------------------------
extern "C" void kernel_launch(void* const* d_in, const int* in_sizes, int n_in,
                              void* d_out, int out_size)
{
    const float* x      = (const float*)d_in[0];
    const float* W1     = (const float*)d_in[1];
    const float* Wrec   = (const float*)d_in[2];
    const float* W2     = (const float*)d_in[3];
    const float* Wout   = (const float*)d_in[4];
    const float* alpha1 = (const float*)d_in[5];
    const float* rho1   = (const float*)d_in[6];
    const float* ba1    = (const float*)d_in[7];
    const float* alpha2 = (const float*)d_in[8];
    const float* rho2   = (const float*)d_in[9];
    const float* ba2    = (const float*)d_in[10];
    const float* betao  = (const float*)d_in[11];
    float* out          = (float*)d_out;

    (void)in_sizes; (void)n_in; (void)out_size;

    const int n_elems = H1_ * H1_ + H1_ * H2_;
    snn_transpose_kernel<<<(n_elems + 255) / 256, 256>>>(Wrec, W2);

    snn_main_kernel<<<B_ / 2, 512>>>(x, W1, Wout,
                                     alpha1, rho1, ba1,
                                     alpha2, rho2, ba2,
                                     betao, out);
}

// round 12
// speedup vs baseline: 2.8997x; 2.8997x over previous
#include <cuda_runtime.h>
#include <cuda_bf16.h>

#define B_  256
#define T_  200
#define C_  40
#define H1_ 512
#define H2_ 256
#define O_  12

// Dynamic SMEM layout (floats):
//   xsh   : 2*T_*C_ = 16000 floats  (both samples' full input, sample-major)
//   maskb : 64 u32  (double-buffered layer-1 spike masks: [parity][sample][16])
//   zsh   : 512 floats (epilogue: folded layer-2 accumulators)
#define XS_FLOATS   (2 * T_ * C_)
#define SMEM_FLOATS (XS_FLOATS + 64 + 512)
#define SMEM_BYTES  (SMEM_FLOATS * 4)

// pack two floats into one 64-bit packed-f32x2 register
static __device__ __forceinline__ unsigned long long pk2(float lo, float hi) {
    unsigned long long r;
    asm("mov.b64 %0, {%1, %2};" : "=l"(r) : "f"(lo), "f"(hi));
    return r;
}

// 40-element dot product: packed weights (20 x f32x2) vs SMEM row at byte-addr `addr`
static __device__ __forceinline__ float dot40(unsigned addr, const unsigned long long* w) {
    unsigned long long acc0 = 0ull, acc1 = 0ull;   // (0.0f, 0.0f) packed
    #pragma unroll
    for (int i = 0; i < 10; i++) {
        unsigned long long p0, p1;
        asm("ld.shared.v2.u64 {%0, %1}, [%2];"
            : "=l"(p0), "=l"(p1) : "r"(addr + 16u * i));
        asm("fma.rn.f32x2 %0, %1, %2, %0;" : "+l"(acc0) : "l"(w[2*i+0]), "l"(p0));
        asm("fma.rn.f32x2 %0, %1, %2, %0;" : "+l"(acc1) : "l"(w[2*i+1]), "l"(p1));
    }
    unsigned long long accs;
    asm("add.rn.f32x2 %0, %1, %2;" : "=l"(accs) : "l"(acc0), "l"(acc1));
    float lo, hi;
    asm("mov.b64 {%0, %1}, %2;" : "=f"(lo), "=f"(hi) : "l"(accs));
    return lo + hi;
}

// ---------------------------------------------------------------------------
// One persistent block per 2 batch samples; full T=200 recurrence in-block.
// 512 threads: thread tid owns layer-1 neuron h=tid (both samples);
// tid<256 additionally owns layer-2 neuron h2=tid (both samples).
// One __syncthreads_or per step (barrier + block-wide "any spike" flag).
// Output layer folded algebraically: out_sum = sum_t (1 - beta^(T-t)) * I_out(t).
// ---------------------------------------------------------------------------
__global__ void __launch_bounds__(512, 1)
snn_main_kernel(const float* __restrict__ x,
                const float* __restrict__ W1,
                const float* __restrict__ Wrec,
                const float* __restrict__ W2,
                const float* __restrict__ Wout,
                const float* __restrict__ alpha1,
                const float* __restrict__ rho1,
                const float* __restrict__ ba1,
                const float* __restrict__ alpha2,
                const float* __restrict__ rho2,
                const float* __restrict__ ba2,
                const float* __restrict__ beta_out,
                float* __restrict__ out)
{
    extern __shared__ float dsm[];
    float*    xsh   = dsm;
    unsigned* maskb = (unsigned*)(dsm + XS_FLOATS);   // [parity*32 + sample*16 + word]
    float*    zsh   = dsm + XS_FLOATS + 64;

    const int tid  = threadIdx.x;
    const int lane = tid & 31;
    const int warp = tid >> 5;
    const int s0   = blockIdx.x * 2;
    const int h    = tid;

    // ---- one-time: preload both samples' x into SMEM (64 KB, coalesced) ----
    {
        const float4* src = (const float4*)(x + (size_t)s0 * (T_ * C_));
        float4*       dst = (float4*)xsh;
        #pragma unroll
        for (int i = tid; i < XS_FLOATS / 4; i += 512) dst[i] = src[i];
    }
    if (tid < 64) maskb[tid] = 0u;

    // ---- one-time: W1 row packed into registers (time-invariant per thread) ----
    unsigned long long w1p[C_ / 2];
    {
        const float4* p = (const float4*)(W1 + h * C_);   // 160B rows, 16B aligned
        #pragma unroll
        for (int i = 0; i < C_ / 4; i++) {
            float4 v = p[i];
            w1p[2*i+0] = pk2(v.x, v.y);
            w1p[2*i+1] = pk2(v.z, v.w);
        }
    }

    // ---- per-thread state & params ----
    const float al1 = alpha1[h], rh1 = rho1[h], bs1 = ba1[h];
    const float om1 = 1.f - al1;
    float v1a = 0.f, v1b = 0.f, a1a = 0.f, a1b = 0.f, spa = 0.f, spb = 0.f;

    float al2 = 0.f, rh2 = 0.f, bs2 = 0.f, om2 = 0.f;
    float v2a = 0.f, v2b = 0.f, a2a = 0.f, a2b = 0.f;
    float zacca = 0.f, zaccb = 0.f;
    if (tid < H2_) {
        al2 = alpha2[tid]; rh2 = rho2[tid]; bs2 = ba2[tid]; om2 = 1.f - al2;
    }

    const float beta  = beta_out[0];
    const float rbeta = 1.f / beta;
    float bp = powf(beta, (float)T_);     // beta^(T-t), t=0

    const unsigned xbase = (unsigned)__cvta_generic_to_shared(xsh);
    int any_prev = 0;

    __syncthreads();   // xsh + masks ready

    for (int t = 0; t < T_; t++) {
        // ---- layer 1: dense input drive (packed-f32x2, register weights) ----
        const unsigned ua = xbase + (unsigned)t * (C_ * 4);
        float I1a = dot40(ua,                 w1p);
        float I1b = dot40(ua + T_ * C_ * 4,   w1p);

        // ---- layer 1: recurrent gather over prev-step spikes (skipped if none) ----
        if (any_prev) {
            const unsigned* mp = &maskb[((t + 1) & 1) * 32];   // parity of t-1
            #pragma unroll 1
            for (int w = 0; w < 16; w++) {
                unsigned m = mp[w];
                while (m) { int j = w*32 + __ffs(m) - 1; I1a += Wrec[h * H1_ + j]; m &= m - 1; }
                m = mp[16 + w];
                while (m) { int j = w*32 + __ffs(m) - 1; I1b += Wrec[h * H1_ + j]; m &= m - 1; }
            }
        }

        // ---- layer 1: state update + spike (TH = 1.0) ----
        v1a = al1 * (v1a - spa) + om1 * (I1a - a1a);
        v1b = al1 * (v1b - spb) + om1 * (I1b - a1b);
        spa = (v1a - 1.0f >= 0.f) ? 1.f : 0.f;
        spb = (v1b - 1.0f >= 0.f) ? 1.f : 0.f;
        a1a = rh1 * a1a + bs1 * spa;
        a1b = rh1 * a1b + bs1 * spb;

        unsigned b1a = __ballot_sync(0xffffffffu, spa > 0.f);
        unsigned b1b = __ballot_sync(0xffffffffu, spb > 0.f);
        if (lane == 0) {
            maskb[(t & 1) * 32 + warp]      = b1a;
            maskb[(t & 1) * 32 + 16 + warp] = b1b;
        }
        // single barrier per step; doubles as block-wide "any layer-1 spike" flag
        int any1 = __syncthreads_or((b1a | b1b) != 0u);

        // ---- layer 2 (tid < 256): gather (rare) + state + folded output ----
        if (tid < H2_) {
            float I2a = 0.f, I2b = 0.f;
            if (any1) {
                const unsigned* mp = &maskb[(t & 1) * 32];
                #pragma unroll 1
                for (int w = 0; w < 16; w++) {
                    unsigned m = mp[w];
                    while (m) { int j = w*32 + __ffs(m) - 1; I2a += W2[tid * H1_ + j]; m &= m - 1; }
                    m = mp[16 + w];
                    while (m) { int j = w*32 + __ffs(m) - 1; I2b += W2[tid * H1_ + j]; m &= m - 1; }
                }
            }
            v2a = al2 * v2a + om2 * (I2a - a2a);          // no reset term (per reference)
            v2b = al2 * v2b + om2 * (I2b - a2b);
            float s2a = (v2a - 1.0f >= 0.f) ? 1.f : 0.f;
            float s2b = (v2b - 1.0f >= 0.f) ? 1.f : 0.f;
            a2a = rh2 * a2a + bs2 * s2a;
            a2b = rh2 * a2b + bs2 * s2b;
            float c = 1.f - bp;                            // 1 - beta^(T-t)
            zacca += c * s2a;
            zaccb += c * s2b;
        }
        bp *= rbeta;
        any_prev = any1;
    }

    // ---- epilogue: out[s,o] = (sum_h2 zacc[s][h2] * Wout[o][h2]) / T ----
    __syncthreads();
    if (tid < H2_) { zsh[tid] = zacca; zsh[H2_ + tid] = zaccb; }
    __syncthreads();

    for (int p = warp; p < 2 * O_; p += 16) {
        const int s = p / O_, o = p % O_;
        float part = 0.f;
        #pragma unroll
        for (int h2 = lane; h2 < H2_; h2 += 32)
            part += zsh[s * H2_ + h2] * Wout[o * H2_ + h2];
        #pragma unroll
        for (int off = 16; off; off >>= 1)
            part += __shfl_xor_sync(0xffffffffu, part, off);
        if (lane == 0)
            out[(s0 + s) * O_ + o] = part / (float)T_;
    }
}

// ---------------------------------------------------------------------------
// Inputs (metadata order): 0:x 1:W1 2:Wrec 3:W2 4:Wout 5:alpha1 6:rho1 7:ba1
//                          8:alpha2 9:rho2 10:ba2 11:beta_out
// Output: float [256, 12]
// ---------------------------------------------------------------------------
extern "C" void kernel_launch(void* const* d_in, const int* in_sizes, int n_in,
                              void* d_out, int out_size)
{
    const float* x      = (const float*)d_in[0];
    const float* W1     = (const float*)d_in[1];
    const float* Wrec   = (const float*)d_in[2];
    const float* W2     = (const float*)d_in[3];
    const float* Wout   = (const float*)d_in[4];
    const float* alpha1 = (const float*)d_in[5];
    const float* rho1   = (const float*)d_in[6];
    const float* ba1    = (const float*)d_in[7];
    const float* alpha2 = (const float*)d_in[8];
    const float* rho2   = (const float*)d_in[9];
    const float* ba2    = (const float*)d_in[10];
    const float* betao  = (const float*)d_in[11];
    float* out          = (float*)d_out;

    (void)in_sizes; (void)n_in; (void)out_size;

    static int smem_set = 0;
    if (!smem_set) {
        cudaFuncSetAttribute(snn_main_kernel,
                             cudaFuncAttributeMaxDynamicSharedMemorySize,
                             SMEM_BYTES);
        smem_set = 1;
    }

    snn_main_kernel<<<B_ / 2, 512, SMEM_BYTES>>>(x, W1, Wrec, W2, Wout,
                                                 alpha1, rho1, ba1,
                                                 alpha2, rho2, ba2,
                                                 betao, out);
}

// round 17
// speedup vs baseline: 7.2131x; 2.4875x over previous
#include <cuda_runtime.h>
#include <cuda_bf16.h>

#define B_  256
#define T_  200
#define C_  40
#define H1_ 512
#define H2_ 256
#define O_  12

// Dynamic SMEM layout (floats):
//   xsh   : 2*T_*C_ = 16000 floats  (both samples' full input)
//   maskb : 64 u32   (fallback path: double-buffered layer-1 spike masks)
//   zsh   : 512 floats (fallback epilogue accumulators)
#define XS_FLOATS   (2 * T_ * C_)
#define SMEM_FLOATS (XS_FLOATS + 64 + 512)
#define SMEM_BYTES  (SMEM_FLOATS * 4)

static __device__ __forceinline__ unsigned long long pk2(float lo, float hi) {
    unsigned long long r;
    asm("mov.b64 %0, {%1, %2};" : "=l"(r) : "f"(lo), "f"(hi));
    return r;
}

// 40-element dot: packed weights (20 x f32x2) vs SMEM row at shared-byte-addr `addr`
static __device__ __forceinline__ float dot40(unsigned addr, const unsigned long long* w) {
    unsigned long long acc0 = 0ull, acc1 = 0ull;
    #pragma unroll
    for (int i = 0; i < 10; i++) {
        unsigned long long p0, p1;
        asm("ld.shared.v2.u64 {%0, %1}, [%2];"
            : "=l"(p0), "=l"(p1) : "r"(addr + 16u * i));
        asm("fma.rn.f32x2 %0, %1, %2, %0;" : "+l"(acc0) : "l"(w[2*i+0]), "l"(p0));
        asm("fma.rn.f32x2 %0, %1, %2, %0;" : "+l"(acc1) : "l"(w[2*i+1]), "l"(p1));
    }
    unsigned long long accs;
    asm("add.rn.f32x2 %0, %1, %2;" : "=l"(accs) : "l"(acc0), "l"(acc1));
    float lo, hi;
    asm("mov.b64 {%0, %1}, %2;" : "=f"(lo), "=f"(hi) : "l"(accs));
    return lo + hi;
}

// ---------------------------------------------------------------------------
// One block per 2 samples. Phase 1 (speculative, barrier-free): run only the
// layer-1 membrane recurrence assuming zero spikes (then a1 == 0 identically
// and v1 = al1*v1 + (1-al1)*I1 is thread-local); track max v1. If no thread
// ever crosses TH=1, the entire reference network output is exactly zero
// (layer-2 zero-input dynamics from zero state stay zero) -> write zeros.
// Phase 2 (fallback, only if any spike fired): full exact algorithm with
// per-step barriers and spike-mask exchange (the previously-passing kernel).
// ---------------------------------------------------------------------------
__global__ void __launch_bounds__(512, 1)
snn_main_kernel(const float* __restrict__ x,
                const float* __restrict__ W1,
                const float* __restrict__ Wrec,
                const float* __restrict__ W2,
                const float* __restrict__ Wout,
                const float* __restrict__ alpha1,
                const float* __restrict__ rho1,
                const float* __restrict__ ba1,
                const float* __restrict__ alpha2,
                const float* __restrict__ rho2,
                const float* __restrict__ ba2,
                const float* __restrict__ beta_out,
                float* __restrict__ out)
{
    extern __shared__ float dsm[];
    float*    xsh   = dsm;
    unsigned* maskb = (unsigned*)(dsm + XS_FLOATS);
    float*    zsh   = dsm + XS_FLOATS + 64;

    const int tid  = threadIdx.x;
    const int lane = tid & 31;
    const int warp = tid >> 5;
    const int s0   = blockIdx.x * 2;
    const int h    = tid;

    // ---- preload both samples' x into SMEM (64 KB, coalesced) ----
    {
        const float4* src = (const float4*)(x + (size_t)s0 * (T_ * C_));
        float4*       dst = (float4*)xsh;
        #pragma unroll
        for (int i = tid; i < XS_FLOATS / 4; i += 512) dst[i] = src[i];
    }
    if (tid < 64) maskb[tid] = 0u;

    // ---- W1 row packed into registers (time-invariant per thread) ----
    unsigned long long w1p[C_ / 2];
    {
        const float4* p = (const float4*)(W1 + h * C_);
        #pragma unroll
        for (int i = 0; i < C_ / 4; i++) {
            float4 v = p[i];
            w1p[2*i+0] = pk2(v.x, v.y);
            w1p[2*i+1] = pk2(v.z, v.w);
        }
    }

    const float al1 = alpha1[h];
    const float om1 = 1.f - al1;
    const unsigned xbase = (unsigned)__cvta_generic_to_shared(xsh);

    __syncthreads();   // xsh ready

    // ================= Phase 1: speculative, barrier-free =================
    {
        float v1a = 0.f, v1b = 0.f, maxv = -1.f;
        #pragma unroll 2
        for (int t = 0; t < T_; t++) {
            const unsigned ua = xbase + (unsigned)t * (C_ * 4);
            float I1a = dot40(ua,               w1p);
            float I1b = dot40(ua + T_ * C_ * 4, w1p);
            v1a = al1 * v1a + om1 * I1a;
            v1b = al1 * v1b + om1 * I1b;
            maxv = fmaxf(maxv, fmaxf(v1a, v1b));
        }
        int any = __syncthreads_or(maxv >= 1.0f);
        if (!any) {
            // no layer-1 spike anywhere -> reference output is exactly zero
            if (tid < 2 * O_)
                out[(size_t)s0 * O_ + tid] = 0.0f;
            return;
        }
    }

    // ================= Phase 2: exact fallback (spikes fired) ==============
    const float rh1 = rho1[h], bs1 = ba1[h];
    float v1a = 0.f, v1b = 0.f, a1a = 0.f, a1b = 0.f, spa = 0.f, spb = 0.f;

    float al2 = 0.f, rh2 = 0.f, bs2 = 0.f, om2 = 0.f;
    float v2a = 0.f, v2b = 0.f, a2a = 0.f, a2b = 0.f;
    float zacca = 0.f, zaccb = 0.f;
    if (tid < H2_) {
        al2 = alpha2[tid]; rh2 = rho2[tid]; bs2 = ba2[tid]; om2 = 1.f - al2;
    }

    const float beta  = beta_out[0];
    const float rbeta = 1.f / beta;
    float bp = powf(beta, (float)T_);     // beta^(T-t) at t=0
    int any_prev = 0;

    __syncthreads();   // masks (zeroed in prologue) visible; state reset done

    for (int t = 0; t < T_; t++) {
        const unsigned ua = xbase + (unsigned)t * (C_ * 4);
        float I1a = dot40(ua,               w1p);
        float I1b = dot40(ua + T_ * C_ * 4, w1p);

        if (any_prev) {
            const unsigned* mp = &maskb[((t + 1) & 1) * 32];
            #pragma unroll 1
            for (int w = 0; w < 16; w++) {
                unsigned m = mp[w];
                while (m) { int j = w*32 + __ffs(m) - 1; I1a += Wrec[h * H1_ + j]; m &= m - 1; }
                m = mp[16 + w];
                while (m) { int j = w*32 + __ffs(m) - 1; I1b += Wrec[h * H1_ + j]; m &= m - 1; }
            }
        }

        v1a = al1 * (v1a - spa) + om1 * (I1a - a1a);   // TH = 1.0
        v1b = al1 * (v1b - spb) + om1 * (I1b - a1b);
        spa = (v1a - 1.0f >= 0.f) ? 1.f : 0.f;
        spb = (v1b - 1.0f >= 0.f) ? 1.f : 0.f;
        a1a = rh1 * a1a + bs1 * spa;
        a1b = rh1 * a1b + bs1 * spb;

        unsigned b1a = __ballot_sync(0xffffffffu, spa > 0.f);
        unsigned b1b = __ballot_sync(0xffffffffu, spb > 0.f);
        if (lane == 0) {
            maskb[(t & 1) * 32 + warp]      = b1a;
            maskb[(t & 1) * 32 + 16 + warp] = b1b;
        }
        int any1 = __syncthreads_or((b1a | b1b) != 0u);

        if (tid < H2_) {
            float I2a = 0.f, I2b = 0.f;
            if (any1) {
                const unsigned* mp = &maskb[(t & 1) * 32];
                #pragma unroll 1
                for (int w = 0; w < 16; w++) {
                    unsigned m = mp[w];
                    while (m) { int j = w*32 + __ffs(m) - 1; I2a += W2[tid * H1_ + j]; m &= m - 1; }
                    m = mp[16 + w];
                    while (m) { int j = w*32 + __ffs(m) - 1; I2b += W2[tid * H1_ + j]; m &= m - 1; }
                }
            }
            v2a = al2 * v2a + om2 * (I2a - a2a);
            v2b = al2 * v2b + om2 * (I2b - a2b);
            float s2a = (v2a - 1.0f >= 0.f) ? 1.f : 0.f;
            float s2b = (v2b - 1.0f >= 0.f) ? 1.f : 0.f;
            a2a = rh2 * a2a + bs2 * s2a;
            a2b = rh2 * a2b + bs2 * s2b;
            float c = 1.f - bp;
            zacca += c * s2a;
            zaccb += c * s2b;
        }
        bp *= rbeta;
        any_prev = any1;
    }

    __syncthreads();
    if (tid < H2_) { zsh[tid] = zacca; zsh[H2_ + tid] = zaccb; }
    __syncthreads();

    for (int p = warp; p < 2 * O_; p += 16) {
        const int s = p / O_, o = p % O_;
        float part = 0.f;
        #pragma unroll
        for (int h2 = lane; h2 < H2_; h2 += 32)
            part += zsh[s * H2_ + h2] * Wout[o * H2_ + h2];
        #pragma unroll
        for (int off = 16; off; off >>= 1)
            part += __shfl_xor_sync(0xffffffffu, part, off);
        if (lane == 0)
            out[(s0 + s) * O_ + o] = part / (float)T_;
    }
}

// ---------------------------------------------------------------------------
// Inputs (metadata order): 0:x 1:W1 2:Wrec 3:W2 4:Wout 5:alpha1 6:rho1 7:ba1
//                          8:alpha2 9:rho2 10:ba2 11:beta_out
// Output: float [256, 12]
// ---------------------------------------------------------------------------
extern "C" void kernel_launch(void* const* d_in, const int* in_sizes, int n_in,
                              void* d_out, int out_size)
{
    const float* x      = (const float*)d_in[0];
    const float* W1     = (const float*)d_in[1];
    const float* Wrec   = (const float*)d_in[2];
    const float* W2     = (const float*)d_in[3];
    const float* Wout   = (const float*)d_in[4];
    const float* alpha1 = (const float*)d_in[5];
    const float* rho1   = (const float*)d_in[6];
    const float* ba1    = (const float*)d_in[7];
    const float* alpha2 = (const float*)d_in[8];
    const float* rho2   = (const float*)d_in[9];
    const float* ba2    = (const float*)d_in[10];
    const float* betao  = (const float*)d_in[11];
    float* out          = (float*)d_out;

    (void)in_sizes; (void)n_in; (void)out_size;

    static int smem_set = 0;
    if (!smem_set) {
        cudaFuncSetAttribute(snn_main_kernel,
                             cudaFuncAttributeMaxDynamicSharedMemorySize,
                             SMEM_BYTES);
        smem_set = 1;
    }

    snn_main_kernel<<<B_ / 2, 512, SMEM_BYTES>>>(x, W1, Wrec, W2, Wout,
                                                 alpha1, rho1, ba1,
                                                 alpha2, rho2, ba2,
                                                 betao, out);
}